// round 6
// baseline (speedup 1.0000x reference)
#include <cuda_runtime.h>
#include <limits.h>

#define N_NODES 100000
#define TPB     256
#define EPS     1e-16f
#define SCAN_BLK 1024
#define NB 98   // ceil(100000/1024)

// ---------------- scratch (device globals; alloc-free) ----------------
__device__ float g_q[N_NODES * 32];
__device__ float g_k[N_NODES * 32];
__device__ float g_v[N_NODES * 32];
__device__ float g_s[N_NODES * 32];
__device__ float g_h[N_NODES * 32];    // layer-1 output
__device__ float g_h2[N_NODES * 16];   // layer-2 output
// CSR
__device__ int g_deg[N_NODES];
__device__ int g_start[N_NODES];
__device__ int g_cur[N_NODES];
__device__ int g_srcs[1700000];
__device__ int g_bsum[NB];
__device__ int g_boff[NB];

// ---------------- CSR build ----------------
__global__ void zero_deg() {
    int i = blockIdx.x * blockDim.x + threadIdx.x;
    if (i < N_NODES) g_deg[i] = 0;
}

__global__ void hist(const int* __restrict__ ei, int E) {
    int e = blockIdx.x * blockDim.x + threadIdx.x;
    if (e < E) atomicAdd(&g_deg[__ldg(ei + E + e)], 1);
}

// per-block scan of g_deg -> block-local exclusive in g_start, block totals
__global__ void scanA() {
    __shared__ int wsum[32];
    int t = threadIdx.x, lane = t & 31, wid = t >> 5;
    int i = blockIdx.x * SCAN_BLK + t;
    int v = (i < N_NODES) ? g_deg[i] : 0;
    int incl = v;
#pragma unroll
    for (int off = 1; off < 32; off <<= 1) {
        int n = __shfl_up_sync(0xffffffffu, incl, off);
        if (lane >= off) incl += n;
    }
    if (lane == 31) wsum[wid] = incl;
    __syncthreads();
    if (wid == 0) {
        int w = wsum[lane];
#pragma unroll
        for (int off = 1; off < 32; off <<= 1) {
            int n = __shfl_up_sync(0xffffffffu, w, off);
            if (lane >= off) w += n;
        }
        wsum[lane] = w;
    }
    __syncthreads();
    int woff = (wid > 0) ? wsum[wid - 1] : 0;
    incl += woff;
    if (i < N_NODES) g_start[i] = incl - v;
    if (t == SCAN_BLK - 1) g_bsum[blockIdx.x] = incl;
}

// exclusive scan of NB block sums
__global__ void scanB() {
    __shared__ int tmp[128];
    int t = threadIdx.x;
    int v = (t < NB) ? g_bsum[t] : 0;
    tmp[t] = v;
    __syncthreads();
    for (int off = 1; off < 128; off <<= 1) {
        int a = 0;
        if (t >= off) a = tmp[t - off];
        __syncthreads();
        tmp[t] += a;
        __syncthreads();
    }
    if (t < NB) g_boff[t] = tmp[t] - v;
}

__global__ void scanC() {
    int i = blockIdx.x * SCAN_BLK + threadIdx.x;
    if (i < N_NODES) {
        int st = g_start[i] + g_boff[blockIdx.x];
        g_start[i] = st;
        g_cur[i] = st;
    }
}

__global__ void scatter(const int* __restrict__ ei, int E) {
    int e = blockIdx.x * blockDim.x + threadIdx.x;
    if (e >= E) return;
    int s = __ldg(ei + e);
    int d = __ldg(ei + E + e);
    int pos = atomicAdd(&g_cur[d], 1);
    g_srcs[pos] = s;
}

// ---------------- layer-1 transform ----------------
__global__ void xform1(const float* __restrict__ x,
                       const float* __restrict__ Wq, const float* __restrict__ bq,
                       const float* __restrict__ Wk, const float* __restrict__ bk,
                       const float* __restrict__ Wv, const float* __restrict__ bv,
                       const float* __restrict__ Ws, const float* __restrict__ bs) {
    __shared__ float sWq[32 * 32], sWk[32 * 32], sWv[32 * 32], sWs[32 * 32];
    __shared__ float sB[4 * 32];
    for (int i = threadIdx.x; i < 32 * 32; i += blockDim.x) {
        sWq[i] = Wq[i]; sWk[i] = Wk[i]; sWv[i] = Wv[i]; sWs[i] = Ws[i];
    }
    for (int i = threadIdx.x; i < 32; i += blockDim.x) {
        sB[i] = bq[i]; sB[32 + i] = bk[i]; sB[64 + i] = bv[i]; sB[96 + i] = bs[i];
    }
    __syncthreads();

    int lane = threadIdx.x & 31;
    int node = (blockIdx.x * blockDim.x + threadIdx.x) >> 5;
    if (node >= N_NODES) return;

    float xv = x[node * 32 + lane];
    float aq = 0.f, ak = 0.f, av = 0.f, as_ = 0.f;
#pragma unroll
    for (int kk = 0; kk < 32; kk++) {
        float xk = __shfl_sync(0xffffffffu, xv, kk);
        aq  += xk * sWq[kk * 32 + lane];
        ak  += xk * sWk[kk * 32 + lane];
        av  += xk * sWv[kk * 32 + lane];
        as_ += xk * sWs[kk * 32 + lane];
    }
    int o = node * 32 + lane;
    g_q[o] = aq  + sB[lane];
    g_k[o] = ak  + sB[32 + lane];
    g_v[o] = av  + sB[64 + lane];
    g_s[o] = as_ + sB[96 + lane];
}

// ---------------- edge aggregation: warp per dst node, no atomics ----------
// G = D/4 lanes per edge slot; NG = 32/G slots per warp.
// UNIFORM trip count across the warp (predicated tail) so full-mask shfls
// are always convergent.  LAYER selects output global.
template <int D, int LAYER>
__global__ void edge_agg(float rscale) {
    constexpr int G  = D / 4;
    constexpr int NG = 32 / G;
    int lane = threadIdx.x & 31;
    int wid  = threadIdx.x >> 5;
    int node = blockIdx.x * 8 + wid;
    if (node >= N_NODES) return;

    int grp = lane / G;      // edge slot within warp
    int sub = lane % G;      // 4-dim chunk within edge

    const float4 qv = *reinterpret_cast<const float4*>(g_q + node * D + sub * 4);

    int start = g_start[node];
    int deg   = g_deg[node];
    int nIter = (deg + NG - 1) / NG;   // same for all lanes of this warp

    float4 acc = make_float4(0.f, 0.f, 0.f, 0.f);
    float wsum = 0.f;

    for (int it = 0; it < nIter; it++) {
        int r = it * NG + grp;
        bool valid = (r < deg);
        int s = valid ? __ldg(g_srcs + start + r) : 0;
        const float4 kv = *reinterpret_cast<const float4*>(g_k + s * D + sub * 4);
        float p = qv.x * kv.x + qv.y * kv.y + qv.z * kv.z + qv.w * kv.w;
#pragma unroll
        for (int off = 1; off < G; off <<= 1)
            p += __shfl_xor_sync(0xffffffffu, p, off);
        float w = valid ? __expf(fminf(p * rscale, 85.0f)) : 0.f;
        wsum += w;
        const float4 vv = *reinterpret_cast<const float4*>(g_v + s * D + sub * 4);
        acc.x += w * vv.x; acc.y += w * vv.y; acc.z += w * vv.z; acc.w += w * vv.w;
    }
    // reduce across edge slots (lanes with equal sub hold the same dims)
#pragma unroll
    for (int off = G; off < 32; off <<= 1) {
        acc.x += __shfl_xor_sync(0xffffffffu, acc.x, off);
        acc.y += __shfl_xor_sync(0xffffffffu, acc.y, off);
        acc.z += __shfl_xor_sync(0xffffffffu, acc.z, off);
        acc.w += __shfl_xor_sync(0xffffffffu, acc.w, off);
        wsum  += __shfl_xor_sync(0xffffffffu, wsum,  off);
    }
    if (lane < G) {
        float rs = 1.0f / (wsum + EPS);
        const float4 sv = *reinterpret_cast<const float4*>(g_s + node * D + lane * 4);
        float4 h;
        h.x = fmaxf(acc.x * rs + sv.x, 0.f);
        h.y = fmaxf(acc.y * rs + sv.y, 0.f);
        h.z = fmaxf(acc.z * rs + sv.z, 0.f);
        h.w = fmaxf(acc.w * rs + sv.w, 0.f);
        float* hout = (LAYER == 0) ? g_h : g_h2;
        *reinterpret_cast<float4*>(hout + node * D + lane * 4) = h;
    }
}

// ---------------- layer-2 transform (reads g_h) ----------------
__global__ void xform2(const float* __restrict__ Wq, const float* __restrict__ bq,
                       const float* __restrict__ Wk, const float* __restrict__ bk,
                       const float* __restrict__ Wv, const float* __restrict__ bv,
                       const float* __restrict__ Ws, const float* __restrict__ bs) {
    __shared__ float sWq[32 * 16], sWk[32 * 16], sWv[32 * 16], sWs[32 * 16];
    __shared__ float sB[4 * 16];
    for (int i = threadIdx.x; i < 32 * 16; i += blockDim.x) {
        sWq[i] = Wq[i]; sWk[i] = Wk[i]; sWv[i] = Wv[i]; sWs[i] = Ws[i];
    }
    for (int i = threadIdx.x; i < 16; i += blockDim.x) {
        sB[i] = bq[i]; sB[16 + i] = bk[i]; sB[32 + i] = bv[i]; sB[48 + i] = bs[i];
    }
    __syncthreads();

    int lane = threadIdx.x & 31;
    int node = (blockIdx.x * blockDim.x + threadIdx.x) >> 5;
    if (node >= N_NODES) return;

    float h = g_h[node * 32 + lane];
    float aq = 0.f, ak = 0.f, av = 0.f, as_ = 0.f;
#pragma unroll
    for (int kk = 0; kk < 32; kk++) {
        float xk = __shfl_sync(0xffffffffu, h, kk);
        if (lane < 16) {
            aq  += xk * sWq[kk * 16 + lane];
            ak  += xk * sWk[kk * 16 + lane];
            av  += xk * sWv[kk * 16 + lane];
            as_ += xk * sWs[kk * 16 + lane];
        }
    }
    if (lane < 16) {
        int o = node * 16 + lane;
        g_q[o] = aq  + sB[lane];
        g_k[o] = ak  + sB[16 + lane];
        g_v[o] = av  + sB[32 + lane];
        g_s[o] = as_ + sB[48 + lane];
    }
}

// ---------------- output head: out = h2 @ Wo + bo ----------------
__global__ void out_head(const float* __restrict__ Wo, const float* __restrict__ bo,
                         float* __restrict__ out) {
    int t = blockIdx.x * blockDim.x + threadIdx.x;
    int node = t >> 4;
    int l = t & 15;
    if (node >= N_NODES) return;

    float h = g_h2[node * 16 + l];
    float p0 = h * __ldg(Wo + l * 2 + 0);
    float p1 = h * __ldg(Wo + l * 2 + 1);
#pragma unroll
    for (int off = 1; off < 16; off <<= 1) {
        p0 += __shfl_xor_sync(0xffffffffu, p0, off);
        p1 += __shfl_xor_sync(0xffffffffu, p1, off);
    }
    if (l == 0) {
        out[node * 2 + 0] = p0 + __ldg(bo + 0);
        out[node * 2 + 1] = p1 + __ldg(bo + 1);
    }
}

extern "C" void kernel_launch(void* const* d_in, const int* in_sizes, int n_in,
                              void* d_out, int out_size) {
    const int*   ei  = (const int*)  d_in[0];
    const float* emb = (const float*)d_in[1];
    const float* Wq1 = (const float*)d_in[2];  const float* bq1 = (const float*)d_in[3];
    const float* Wk1 = (const float*)d_in[4];  const float* bk1 = (const float*)d_in[5];
    const float* Wv1 = (const float*)d_in[6];  const float* bv1 = (const float*)d_in[7];
    const float* Ws1 = (const float*)d_in[8];  const float* bs1 = (const float*)d_in[9];
    const float* Wq2 = (const float*)d_in[10]; const float* bq2 = (const float*)d_in[11];
    const float* Wk2 = (const float*)d_in[12]; const float* bk2 = (const float*)d_in[13];
    const float* Wv2 = (const float*)d_in[14]; const float* bv2 = (const float*)d_in[15];
    const float* Ws2 = (const float*)d_in[16]; const float* bs2 = (const float*)d_in[17];
    const float* Wo  = (const float*)d_in[18]; const float* bo  = (const float*)d_in[19];
    float* out = (float*)d_out;

    int E = in_sizes[0] / 2;
    int eBlocks    = (E + TPB - 1) / TPB;
    int nBlocks    = (N_NODES + TPB - 1) / TPB;
    int nodeBlocks = (N_NODES * 32 + TPB - 1) / TPB;
    int aggBlocks  = (N_NODES + 7) / 8;   // 8 warps (nodes) per block

    // ---- CSR build (once; reused by both layers) ----
    zero_deg<<<nBlocks, TPB>>>();
    hist<<<eBlocks, TPB>>>(ei, E);
    scanA<<<NB, SCAN_BLK>>>();
    scanB<<<1, 128>>>();
    scanC<<<NB, SCAN_BLK>>>();
    scatter<<<eBlocks, TPB>>>(ei, E);

    // ---- layer 1 (D=32) ----
    xform1<<<nodeBlocks, TPB>>>(emb, Wq1, bq1, Wk1, bk1, Wv1, bv1, Ws1, bs1);
    edge_agg<32, 0><<<aggBlocks, TPB>>>(0.17677669529663687f);  // 1/sqrt(32)

    // ---- layer 2 (D=16) ----
    xform2<<<nodeBlocks, TPB>>>(Wq2, bq2, Wk2, bk2, Wv2, bv2, Ws2, bs2);
    edge_agg<16, 1><<<aggBlocks, TPB>>>(0.25f);                 // 1/sqrt(16)

    // ---- output head ----
    out_head<<<(N_NODES * 16 + TPB - 1) / TPB, TPB>>>(Wo, bo, out);
}

// round 7
// speedup vs baseline: 1.1551x; 1.1551x over previous
#include <cuda_runtime.h>
#include <limits.h>

#define N_NODES 100000
#define TPB     256
#define EPS     1e-16f
#define SCAN_BLK 1024
#define NB 98   // ceil(100000/1024)
#define CHUNK 16

// ---------------- scratch (device globals; alloc-free) ----------------
__device__ float g_q[N_NODES * 32];
__device__ float g_k[N_NODES * 32];
__device__ float g_v[N_NODES * 32];
__device__ float g_s[N_NODES * 32];
__device__ float g_sum[N_NODES];
__device__ float g_agg[N_NODES * 32];
__device__ float g_h[N_NODES * 32];
__device__ float g_h2[N_NODES * 16];
// sorted edge list (by dst)
__device__ int g_deg[N_NODES];
__device__ int g_start[N_NODES];
__device__ int g_cur[N_NODES];
__device__ int g_srcs[1700000];
__device__ int g_dsts[1700000];
__device__ int g_bsum[NB];
__device__ int g_boff[NB];

// ---------------- sort-by-dst build ----------------
__global__ void zero_deg() {
    int i = blockIdx.x * blockDim.x + threadIdx.x;
    if (i < N_NODES) g_deg[i] = 0;
}

__global__ void hist(const int* __restrict__ ei, int E) {
    int e = blockIdx.x * blockDim.x + threadIdx.x;
    if (e < E) atomicAdd(&g_deg[__ldg(ei + E + e)], 1);
}

__global__ void scanA() {
    __shared__ int wsum[32];
    int t = threadIdx.x, lane = t & 31, wid = t >> 5;
    int i = blockIdx.x * SCAN_BLK + t;
    int v = (i < N_NODES) ? g_deg[i] : 0;
    int incl = v;
#pragma unroll
    for (int off = 1; off < 32; off <<= 1) {
        int n = __shfl_up_sync(0xffffffffu, incl, off);
        if (lane >= off) incl += n;
    }
    if (lane == 31) wsum[wid] = incl;
    __syncthreads();
    if (wid == 0) {
        int w = wsum[lane];
#pragma unroll
        for (int off = 1; off < 32; off <<= 1) {
            int n = __shfl_up_sync(0xffffffffu, w, off);
            if (lane >= off) w += n;
        }
        wsum[lane] = w;
    }
    __syncthreads();
    int woff = (wid > 0) ? wsum[wid - 1] : 0;
    incl += woff;
    if (i < N_NODES) g_start[i] = incl - v;
    if (t == SCAN_BLK - 1) g_bsum[blockIdx.x] = incl;
}

__global__ void scanB() {
    __shared__ int tmp[128];
    int t = threadIdx.x;
    int v = (t < NB) ? g_bsum[t] : 0;
    tmp[t] = v;
    __syncthreads();
    for (int off = 1; off < 128; off <<= 1) {
        int a = 0;
        if (t >= off) a = tmp[t - off];
        __syncthreads();
        tmp[t] += a;
        __syncthreads();
    }
    if (t < NB) g_boff[t] = tmp[t] - v;
}

__global__ void scanC() {
    int i = blockIdx.x * SCAN_BLK + threadIdx.x;
    if (i < N_NODES) g_cur[i] = g_start[i] + g_boff[blockIdx.x];
}

__global__ void scatter(const int* __restrict__ ei, int E) {
    int e = blockIdx.x * blockDim.x + threadIdx.x;
    if (e >= E) return;
    int s = __ldg(ei + e);
    int d = __ldg(ei + E + e);
    int pos = atomicAdd(&g_cur[d], 1);
    g_srcs[pos] = s;
    g_dsts[pos] = d;
}

// ---------------- layer-1 transform + zero agg/sum ----------------
__global__ void xform1(const float* __restrict__ x,
                       const float* __restrict__ Wq, const float* __restrict__ bq,
                       const float* __restrict__ Wk, const float* __restrict__ bk,
                       const float* __restrict__ Wv, const float* __restrict__ bv,
                       const float* __restrict__ Ws, const float* __restrict__ bs) {
    __shared__ float sWq[32 * 32], sWk[32 * 32], sWv[32 * 32], sWs[32 * 32];
    __shared__ float sB[4 * 32];
    for (int i = threadIdx.x; i < 32 * 32; i += blockDim.x) {
        sWq[i] = Wq[i]; sWk[i] = Wk[i]; sWv[i] = Wv[i]; sWs[i] = Ws[i];
    }
    for (int i = threadIdx.x; i < 32; i += blockDim.x) {
        sB[i] = bq[i]; sB[32 + i] = bk[i]; sB[64 + i] = bv[i]; sB[96 + i] = bs[i];
    }
    __syncthreads();

    int lane = threadIdx.x & 31;
    int node = (blockIdx.x * blockDim.x + threadIdx.x) >> 5;
    if (node >= N_NODES) return;

    float xv = x[node * 32 + lane];
    float aq = 0.f, ak = 0.f, av = 0.f, as_ = 0.f;
#pragma unroll
    for (int kk = 0; kk < 32; kk++) {
        float xk = __shfl_sync(0xffffffffu, xv, kk);
        aq  += xk * sWq[kk * 32 + lane];
        ak  += xk * sWk[kk * 32 + lane];
        av  += xk * sWv[kk * 32 + lane];
        as_ += xk * sWs[kk * 32 + lane];
    }
    int o = node * 32 + lane;
    g_q[o] = aq  + sB[lane];
    g_k[o] = ak  + sB[32 + lane];
    g_v[o] = av  + sB[64 + lane];
    g_s[o] = as_ + sB[96 + lane];
    g_agg[o] = 0.f;
    if (lane == 0) g_sum[node] = 0.f;
}

// ---------------- segmented edge reduce over dst-sorted edges --------------
// G = D/4 lanes per edge group; each group walks CHUNK consecutive sorted
// edges, accumulating while dst unchanged, flushing with float4 atomics on
// run boundaries.  Loop trip count uniform across warp -> full-mask shfls OK.
template <int D>
__global__ void edge_seg(int E, float rscale) {
    constexpr int G  = D / 4;
    constexpr int NG = 32 / G;
    int lane = threadIdx.x & 31;
    int wid  = threadIdx.x >> 5;
    int grp  = lane / G;
    int sub  = lane % G;

    int base = (((blockIdx.x * 8 + wid) * NG) + grp) * CHUNK;

    float4 acc = make_float4(0.f, 0.f, 0.f, 0.f);
    float  wsum = 0.f;
    int    prev_d = -1;
    float4 qv = make_float4(0.f, 0.f, 0.f, 0.f);

    for (int it = 0; it < CHUNK; it++) {
        int e = base + it;
        bool valid = (e < E);
        int d = valid ? __ldg(g_dsts + e) : prev_d;
        int s = valid ? __ldg(g_srcs + e) : 0;

        if (d != prev_d) {
            if (prev_d >= 0) {
                atomicAdd(reinterpret_cast<float4*>(g_agg + prev_d * D + sub * 4), acc);
                if (sub == 0) atomicAdd(&g_sum[prev_d], wsum);
            }
            acc = make_float4(0.f, 0.f, 0.f, 0.f);
            wsum = 0.f;
            prev_d = d;
            qv = *reinterpret_cast<const float4*>(g_q + d * D + sub * 4);
        }

        const float4 kv = *reinterpret_cast<const float4*>(g_k + s * D + sub * 4);
        float p = qv.x * kv.x + qv.y * kv.y + qv.z * kv.z + qv.w * kv.w;
#pragma unroll
        for (int off = 1; off < G; off <<= 1)
            p += __shfl_xor_sync(0xffffffffu, p, off);
        float w = valid ? __expf(fminf(p * rscale, 85.0f)) : 0.f;
        wsum += w;
        const float4 vv = *reinterpret_cast<const float4*>(g_v + s * D + sub * 4);
        acc.x += w * vv.x; acc.y += w * vv.y; acc.z += w * vv.z; acc.w += w * vv.w;
    }
    if (prev_d >= 0) {
        atomicAdd(reinterpret_cast<float4*>(g_agg + prev_d * D + sub * 4), acc);
        if (sub == 0) atomicAdd(&g_sum[prev_d], wsum);
    }
}

// ---------------- finish layer 1 + layer-2 transform + re-zero -------------
__global__ void finish1_xform2(const float* __restrict__ Wq, const float* __restrict__ bq,
                               const float* __restrict__ Wk, const float* __restrict__ bk,
                               const float* __restrict__ Wv, const float* __restrict__ bv,
                               const float* __restrict__ Ws, const float* __restrict__ bs) {
    __shared__ float sWq[32 * 16], sWk[32 * 16], sWv[32 * 16], sWs[32 * 16];
    __shared__ float sB[4 * 16];
    for (int i = threadIdx.x; i < 32 * 16; i += blockDim.x) {
        sWq[i] = Wq[i]; sWk[i] = Wk[i]; sWv[i] = Wv[i]; sWs[i] = Ws[i];
    }
    for (int i = threadIdx.x; i < 16; i += blockDim.x) {
        sB[i] = bq[i]; sB[16 + i] = bk[i]; sB[32 + i] = bv[i]; sB[48 + i] = bs[i];
    }
    __syncthreads();

    int lane = threadIdx.x & 31;
    int node = (blockIdx.x * blockDim.x + threadIdx.x) >> 5;
    if (node >= N_NODES) return;

    int o32 = node * 32 + lane;
    float rs = 1.0f / (g_sum[node] + EPS);
    float h  = g_agg[o32] * rs + g_s[o32];
    h = h > 0.f ? h : 0.f;

    g_agg[o32] = 0.f;
    if (lane == 0) g_sum[node] = 0.f;

    float aq = 0.f, ak = 0.f, av = 0.f, as_ = 0.f;
#pragma unroll
    for (int kk = 0; kk < 32; kk++) {
        float xk = __shfl_sync(0xffffffffu, h, kk);
        if (lane < 16) {
            aq  += xk * sWq[kk * 16 + lane];
            ak  += xk * sWk[kk * 16 + lane];
            av  += xk * sWv[kk * 16 + lane];
            as_ += xk * sWs[kk * 16 + lane];
        }
    }
    if (lane < 16) {
        int o = node * 16 + lane;
        g_q[o] = aq  + sB[lane];
        g_k[o] = ak  + sB[16 + lane];
        g_v[o] = av  + sB[32 + lane];
        g_s[o] = as_ + sB[48 + lane];
    }
}

// ---------------- finish layer 2 + output head -----------------------------
__global__ void finish2_out(const float* __restrict__ Wo, const float* __restrict__ bo,
                            float* __restrict__ out) {
    int t = blockIdx.x * blockDim.x + threadIdx.x;
    int node = t >> 4;
    int l = t & 15;
    if (node >= N_NODES) return;

    int o = node * 16 + l;
    float rs = 1.0f / (g_sum[node] + EPS);
    float h = g_agg[o] * rs + g_s[o];
    h = h > 0.f ? h : 0.f;

    float p0 = h * __ldg(Wo + l * 2 + 0);
    float p1 = h * __ldg(Wo + l * 2 + 1);
#pragma unroll
    for (int off = 1; off < 16; off <<= 1) {
        p0 += __shfl_xor_sync(0xffffffffu, p0, off);
        p1 += __shfl_xor_sync(0xffffffffu, p1, off);
    }
    if (l == 0) {
        out[node * 2 + 0] = p0 + __ldg(bo + 0);
        out[node * 2 + 1] = p1 + __ldg(bo + 1);
    }
}

extern "C" void kernel_launch(void* const* d_in, const int* in_sizes, int n_in,
                              void* d_out, int out_size) {
    const int*   ei  = (const int*)  d_in[0];
    const float* emb = (const float*)d_in[1];
    const float* Wq1 = (const float*)d_in[2];  const float* bq1 = (const float*)d_in[3];
    const float* Wk1 = (const float*)d_in[4];  const float* bk1 = (const float*)d_in[5];
    const float* Wv1 = (const float*)d_in[6];  const float* bv1 = (const float*)d_in[7];
    const float* Ws1 = (const float*)d_in[8];  const float* bs1 = (const float*)d_in[9];
    const float* Wq2 = (const float*)d_in[10]; const float* bq2 = (const float*)d_in[11];
    const float* Wk2 = (const float*)d_in[12]; const float* bk2 = (const float*)d_in[13];
    const float* Wv2 = (const float*)d_in[14]; const float* bv2 = (const float*)d_in[15];
    const float* Ws2 = (const float*)d_in[16]; const float* bs2 = (const float*)d_in[17];
    const float* Wo  = (const float*)d_in[18]; const float* bo  = (const float*)d_in[19];
    float* out = (float*)d_out;

    int E = in_sizes[0] / 2;
    int eBlocks    = (E + TPB - 1) / TPB;
    int nBlocks    = (N_NODES + TPB - 1) / TPB;
    int nodeBlocks = (N_NODES * 32 + TPB - 1) / TPB;
    // D=32: 8 warps * 4 groups * CHUNK edges per block
    int segBlocks32 = (E + 8 * 4 * CHUNK - 1) / (8 * 4 * CHUNK);
    int segBlocks16 = (E + 8 * 8 * CHUNK - 1) / (8 * 8 * CHUNK);

    // ---- sort edges by dst (once; reused by both layers) ----
    zero_deg<<<nBlocks, TPB>>>();
    hist<<<eBlocks, TPB>>>(ei, E);
    scanA<<<NB, SCAN_BLK>>>();
    scanB<<<1, 128>>>();
    scanC<<<NB, SCAN_BLK>>>();
    scatter<<<eBlocks, TPB>>>(ei, E);

    // ---- layer 1 (D=32) ----
    xform1<<<nodeBlocks, TPB>>>(emb, Wq1, bq1, Wk1, bk1, Wv1, bv1, Ws1, bs1);
    edge_seg<32><<<segBlocks32, TPB>>>(E, 0.17677669529663687f);  // 1/sqrt(32)

    // ---- layer 2 (D=16) ----
    finish1_xform2<<<nodeBlocks, TPB>>>(Wq2, bq2, Wk2, bk2, Wv2, bv2, Ws2, bs2);
    edge_seg<16><<<segBlocks16, TPB>>>(E, 0.25f);                 // 1/sqrt(16)

    // ---- output head ----
    finish2_out<<<(N_NODES * 16 + TPB - 1) / TPB, TPB>>>(Wo, bo, out);
}